// round 2
// baseline (speedup 1.0000x reference)
#include <cuda_runtime.h>

// Problem constants
#define S_LEN 2048
#define EMB   1024
#define HEADS 16
#define DH    64
#define BATCH 2

// Scratch (no allocations allowed): qkv = [B,S,3E], ctx = [B,S,E]
__device__ float g_qkv[(size_t)BATCH * S_LEN * 3 * EMB];
__device__ float g_ctx[(size_t)BATCH * S_LEN * EMB];

// ---------------------------------------------------------------------------
// Swizzled smem indexing (float4 granularity). Row stride = 16 float4.
// phys_c4 = c4 ^ ((row>>2)&15) spreads row-strided accesses across banks.
// ---------------------------------------------------------------------------
__device__ __forceinline__ int SW(int r, int c4) {
    return r * 16 + (c4 ^ ((r >> 2) & 15));
}

__device__ __forceinline__ void fma4(float4& o, float a, const float4 v) {
    o.x += a * v.x; o.y += a * v.y; o.z += a * v.z; o.w += a * v.w;
}

// ---------------------------------------------------------------------------
// C[M,N] = A[M,K] @ B[N,K]^T + bias[N]
// 128x128 tile, K-step 8, 256 threads, 8x8 per-thread microtile.
// All dims divisible by tile sizes for this problem (M=4096, N in {3072,1024}, K=1024).
// ---------------------------------------------------------------------------
__global__ __launch_bounds__(256) void gemm_nt_bias(
    const float* __restrict__ A, const float* __restrict__ B,
    const float* __restrict__ bias, float* __restrict__ C,
    int M, int N, int K)
{
    __shared__ float As[8][128];
    __shared__ float Bs[8][128];

    const int tid = threadIdx.x;
    const int bm  = blockIdx.y * 128;
    const int bn  = blockIdx.x * 128;
    const int lr  = tid >> 1;          // 0..127 (tile row for loading)
    const int lc  = (tid & 1) * 4;     // 0 or 4 (k offset for loading)
    const int ty  = tid >> 4;          // 0..15
    const int tx  = tid & 15;          // 0..15

    float acc[8][8];
    #pragma unroll
    for (int i = 0; i < 8; i++)
        #pragma unroll
        for (int j = 0; j < 8; j++)
            acc[i][j] = 0.0f;

    const float* Ap = A + (size_t)(bm + lr) * K + lc;
    const float* Bp = B + (size_t)(bn + lr) * K + lc;

    for (int k0 = 0; k0 < K; k0 += 8) {
        float4 av = *(const float4*)(Ap + k0);
        float4 bv = *(const float4*)(Bp + k0);
        __syncthreads();
        As[lc + 0][lr] = av.x; As[lc + 1][lr] = av.y;
        As[lc + 2][lr] = av.z; As[lc + 3][lr] = av.w;
        Bs[lc + 0][lr] = bv.x; Bs[lc + 1][lr] = bv.y;
        Bs[lc + 2][lr] = bv.z; Bs[lc + 3][lr] = bv.w;
        __syncthreads();

        #pragma unroll
        for (int kk = 0; kk < 8; kk++) {
            float a[8], b[8];
            *(float4*)&a[0] = *(const float4*)&As[kk][ty * 8];
            *(float4*)&a[4] = *(const float4*)&As[kk][ty * 8 + 4];
            *(float4*)&b[0] = *(const float4*)&Bs[kk][tx * 8];
            *(float4*)&b[4] = *(const float4*)&Bs[kk][tx * 8 + 4];
            #pragma unroll
            for (int i = 0; i < 8; i++)
                #pragma unroll
                for (int j = 0; j < 8; j++)
                    acc[i][j] += a[i] * b[j];
        }
    }

    #pragma unroll
    for (int i = 0; i < 8; i++) {
        const size_t row = (size_t)(bm + ty * 8 + i);
        #pragma unroll
        for (int j4 = 0; j4 < 2; j4++) {
            const int col = bn + tx * 8 + j4 * 4;
            float4 o;
            o.x = acc[i][j4 * 4 + 0] + bias[col + 0];
            o.y = acc[i][j4 * 4 + 1] + bias[col + 1];
            o.z = acc[i][j4 * 4 + 2] + bias[col + 2];
            o.w = acc[i][j4 * 4 + 3] + bias[col + 3];
            *(float4*)&C[row * N + col] = o;
        }
    }
}

// ---------------------------------------------------------------------------
// Fused causal attention (flash-style, fp32), one block per (q-tile of 64, b*h).
// 256 threads as 16x16; each thread owns a 4(q) x 4(k) score microtile and a
// 4(q) x 4(d) output microtile. Online softmax with warp-shuffle row reduction
// (rows are distributed over the 16 tx lanes, which sit inside one half-warp).
// K smem buffer is reused to hold P after the scores are consumed (fits 48KB).
// ---------------------------------------------------------------------------
__global__ __launch_bounds__(256) void attn_kernel(
    const float* __restrict__ qkv, float* __restrict__ ctx)
{
    __shared__ float4 Qs [64 * 16];
    __shared__ float4 KPs[64 * 16];   // K tile, then reused for P
    __shared__ float4 Vs [64 * 16];

    const int qt  = blockIdx.x;       // 0..31 query tile
    const int bh  = blockIdx.y;       // 0..31
    const int b   = bh >> 4;
    const int h   = bh & 15;
    const int tid = threadIdx.x;
    const int ty  = tid >> 4;         // 0..15 -> q rows 4ty..4ty+3
    const int tx  = tid & 15;         // 0..15 -> k cols / d cols 4tx..4tx+3

    const float* base = qkv + (size_t)b * S_LEN * (3 * EMB);
    const int qoff = h * DH;
    const int koff = EMB + h * DH;
    const int voff = 2 * EMB + h * DH;

    // Load Q tile (64 rows x 64 dims) as float4, swizzled.
    #pragma unroll
    for (int i = 0; i < 4; i++) {
        const int idx = tid + 256 * i;
        const int r = idx >> 4, c4 = idx & 15;
        Qs[SW(r, c4)] = *(const float4*)(base + (size_t)(qt * 64 + r) * (3 * EMB) + qoff + c4 * 4);
    }

    const float scale = 0.125f;  // 64^-0.5
    float  m[4], l[4];
    float4 oacc[4];
    #pragma unroll
    for (int r = 0; r < 4; r++) {
        m[r] = -1e30f;
        l[r] = 0.0f;
        oacc[r] = make_float4(0.f, 0.f, 0.f, 0.f);
    }

    for (int kt = 0; kt <= qt; kt++) {
        __syncthreads();  // previous-iteration readers of KPs/Vs (and Q store at kt=0) done

        // Load K and V tiles
        #pragma unroll
        for (int i = 0; i < 4; i++) {
            const int idx = tid + 256 * i;
            const int r = idx >> 4, c4 = idx & 15;
            const float* rowp = base + (size_t)(kt * 64 + r) * (3 * EMB);
            KPs[SW(r, c4)] = *(const float4*)(rowp + koff + c4 * 4);
            Vs [SW(r, c4)] = *(const float4*)(rowp + voff + c4 * 4);
        }
        __syncthreads();

        // S = Q K^T (this thread: q rows 4ty+r, k rows 4tx+c)
        float s[4][4];
        #pragma unroll
        for (int r = 0; r < 4; r++)
            #pragma unroll
            for (int c = 0; c < 4; c++)
                s[r][c] = 0.0f;

        #pragma unroll
        for (int k4 = 0; k4 < 16; k4++) {
            float4 q[4], kk[4];
            #pragma unroll
            for (int r = 0; r < 4; r++) q[r]  = Qs [SW(4 * ty + r, k4)];
            #pragma unroll
            for (int c = 0; c < 4; c++) kk[c] = KPs[SW(4 * tx + c, k4)];
            #pragma unroll
            for (int r = 0; r < 4; r++)
                #pragma unroll
                for (int c = 0; c < 4; c++)
                    s[r][c] += q[r].x * kk[c].x + q[r].y * kk[c].y
                             + q[r].z * kk[c].z + q[r].w * kk[c].w;
        }

        // Scale + causal mask (only the diagonal tile is partially masked)
        #pragma unroll
        for (int r = 0; r < 4; r++)
            #pragma unroll
            for (int c = 0; c < 4; c++) {
                s[r][c] *= scale;
                if (kt == qt && (4 * tx + c) > (4 * ty + r)) s[r][c] = -1e30f;
            }

        // Row max over the 16 tx lanes (xor shuffles stay within half-warp)
        float mt[4];
        #pragma unroll
        for (int r = 0; r < 4; r++) {
            mt[r] = fmaxf(fmaxf(s[r][0], s[r][1]), fmaxf(s[r][2], s[r][3]));
            #pragma unroll
            for (int o = 8; o > 0; o >>= 1)
                mt[r] = fmaxf(mt[r], __shfl_xor_sync(0xffffffffu, mt[r], o));
        }

        // Online softmax update
        float p[4][4];
        #pragma unroll
        for (int r = 0; r < 4; r++) {
            const float mnew = fmaxf(m[r], mt[r]);
            const float corr = __expf(m[r] - mnew);
            float rs = 0.0f;
            #pragma unroll
            for (int c = 0; c < 4; c++) {
                p[r][c] = __expf(s[r][c] - mnew);
                rs += p[r][c];
            }
            #pragma unroll
            for (int o = 8; o > 0; o >>= 1)
                rs += __shfl_xor_sync(0xffffffffu, rs, o);
            l[r] = l[r] * corr + rs;
            m[r] = mnew;
            oacc[r].x *= corr; oacc[r].y *= corr; oacc[r].z *= corr; oacc[r].w *= corr;
        }

        __syncthreads();  // everyone done reading K from KPs
        #pragma unroll
        for (int r = 0; r < 4; r++)
            KPs[SW(4 * ty + r, tx)] = make_float4(p[r][0], p[r][1], p[r][2], p[r][3]);
        __syncthreads();

        // O += P @ V  (this thread: q rows 4ty+r, d cols 4tx..4tx+3)
        #pragma unroll
        for (int k4 = 0; k4 < 16; k4++) {
            float4 pv[4];
            #pragma unroll
            for (int r = 0; r < 4; r++) pv[r] = KPs[SW(4 * ty + r, k4)];
            const float4 v0 = Vs[SW(4 * k4 + 0, tx)];
            const float4 v1 = Vs[SW(4 * k4 + 1, tx)];
            const float4 v2 = Vs[SW(4 * k4 + 2, tx)];
            const float4 v3 = Vs[SW(4 * k4 + 3, tx)];
            #pragma unroll
            for (int r = 0; r < 4; r++) {
                fma4(oacc[r], pv[r].x, v0);
                fma4(oacc[r], pv[r].y, v1);
                fma4(oacc[r], pv[r].z, v2);
                fma4(oacc[r], pv[r].w, v3);
            }
        }
    }

    // Normalize and write ctx[b, q, h*64 + 4tx .. +3]
    #pragma unroll
    for (int r = 0; r < 4; r++) {
        const float inv = 1.0f / l[r];
        float4 o = oacc[r];
        o.x *= inv; o.y *= inv; o.z *= inv; o.w *= inv;
        const size_t row = (size_t)b * S_LEN + qt * 64 + 4 * ty + r;
        *(float4*)&ctx[row * EMB + h * DH + 4 * tx] = o;
    }
}

// ---------------------------------------------------------------------------
// Launch: qkv-proj GEMM -> fused attention -> out-proj GEMM
// ---------------------------------------------------------------------------
extern "C" void kernel_launch(void* const* d_in, const int* in_sizes, int n_in,
                              void* d_out, int out_size)
{
    const float* x     = (const float*)d_in[0];
    const float* w_in  = (const float*)d_in[1];
    const float* b_in  = (const float*)d_in[2];
    const float* w_out = (const float*)d_in[3];
    const float* b_out = (const float*)d_in[4];
    float* out = (float*)d_out;

    float *qkv = nullptr, *ctx = nullptr;
    cudaGetSymbolAddress((void**)&qkv, g_qkv);
    cudaGetSymbolAddress((void**)&ctx, g_ctx);

    const int M = BATCH * S_LEN;   // 4096

    // 1) qkv = x @ in_proj_w^T + in_proj_b   [4096, 3072]
    gemm_nt_bias<<<dim3((3 * EMB) / 128, M / 128), 256>>>(
        x, w_in, b_in, qkv, M, 3 * EMB, EMB);

    // 2) fused causal attention -> ctx [4096, 1024]
    attn_kernel<<<dim3(S_LEN / 64, BATCH * HEADS), 256>>>(qkv, ctx);

    // 3) out = ctx @ out_proj_w^T + out_proj_b   [4096, 1024]
    gemm_nt_bias<<<dim3(EMB / 128, M / 128), 256>>>(
        ctx, w_out, b_out, out, M, EMB, EMB);
}

// round 4
// speedup vs baseline: 1.6086x; 1.6086x over previous
#include <cuda_runtime.h>
#include <cstdint>

// Problem constants
#define S_LEN 2048
#define EMB   1024
#define HEADS 16
#define DH    64
#define BATCH 2

// Scratch (no allocations allowed): qkv = [B,S,3E], ctx = [B,S,E]
__device__ float g_qkv[(size_t)BATCH * S_LEN * 3 * EMB];
__device__ float g_ctx[(size_t)BATCH * S_LEN * EMB];

// ===========================================================================
// Helpers
// ===========================================================================
__device__ __forceinline__ uint32_t smem_u32(const void* p) {
    uint32_t a;
    asm("{ .reg .u64 t; cvta.to.shared.u64 t, %1; cvt.u32.u64 %0, t; }"
        : "=r"(a) : "l"(p));
    return a;
}

__device__ __forceinline__ void cp_async16(uint32_t dst, const void* src) {
    asm volatile("cp.async.cg.shared.global [%0], [%1], 16;"
                 :: "r"(dst), "l"(src));
}
#define CP_COMMIT() asm volatile("cp.async.commit_group;")
#define CP_WAIT1()  asm volatile("cp.async.wait_group 1;")
#define CP_WAIT0()  asm volatile("cp.async.wait_group 0;")

__device__ __forceinline__ uint32_t f2tf32(float f) {
    uint32_t r;
    asm("cvt.rna.tf32.f32 %0, %1;" : "=r"(r) : "f"(f));
    return r;
}

// mma.sync m16n8k8 tf32: D += A*B, fp32 accumulate
__device__ __forceinline__ void mma_tf32(
    float* c, const uint32_t* a, const uint32_t* b)
{
    asm volatile(
        "mma.sync.aligned.m16n8k8.row.col.f32.tf32.tf32.f32 "
        "{%0,%1,%2,%3}, {%4,%5,%6,%7}, {%8,%9}, {%0,%1,%2,%3};"
        : "+f"(c[0]), "+f"(c[1]), "+f"(c[2]), "+f"(c[3])
        : "r"(a[0]), "r"(a[1]), "r"(a[2]), "r"(a[3]), "r"(b[0]), "r"(b[1]));
}

// ===========================================================================
// tf32 tensor-core GEMM:  C[M,N] = A[M,K] @ B[N,K]^T + bias[N]
// 128x128 CTA tile, 8 warps (2M x 4N), each warp 64x32 via 4x4 m16n8k8 frags.
// K-chunks of 32, cp.async double-buffered smem pipeline. Rows padded to 36
// floats so fragment loads ((4g+tig) mod 32) are bank-conflict-free.
// ===========================================================================
#define PAD     36
#define TILE_F  (128 * PAD)           // floats per A (or B) tile
#define BUF_F   (2 * TILE_F)          // A tile + B tile per stage
#define GM_SMEM (2 * BUF_F * 4)       // bytes, two stages = 73728

__global__ __launch_bounds__(256) void gemm_mma(
    const float* __restrict__ A, const float* __restrict__ B,
    const float* __restrict__ bias, float* __restrict__ C,
    int M, int N, int K)
{
    extern __shared__ float smem[];
    const int tid  = threadIdx.x;
    const int wid  = tid >> 5;
    const int lane = tid & 31;
    const int wm   = wid >> 2;        // 0..1  -> 64-row band
    const int wn   = wid & 3;         // 0..3  -> 32-col band
    const int g    = lane >> 2;       // 0..7
    const int tig  = lane & 3;        // 0..3
    const int bm   = blockIdx.y * 128;
    const int bn   = blockIdx.x * 128;

    float acc[4][4][4];
    #pragma unroll
    for (int mt = 0; mt < 4; mt++)
        #pragma unroll
        for (int nt = 0; nt < 4; nt++)
            #pragma unroll
            for (int i = 0; i < 4; i++)
                acc[mt][nt][i] = 0.0f;

    // Per-thread global/shared fill coordinates (8 x 16B per chunk)
    const int fr = tid >> 3;          // wait — see fill loop below (id-based)

    auto fill = [&](int buf, int kc) {
        const int k0 = kc << 5;
        const uint32_t sA = smem_u32(smem + buf * BUF_F);
        const uint32_t sB = sA + TILE_F * 4;
        #pragma unroll
        for (int i = 0; i < 4; i++) {
            const int id = tid + (i << 8);    // 0..1023
            const int r  = id >> 3;           // 0..127
            const int c  = id & 7;            // 0..7 (float4 within 32-float row)
            const uint32_t so = (uint32_t)(r * PAD + c * 4) * 4;
            cp_async16(sA + so, A + (size_t)(bm + r) * K + k0 + c * 4);
            cp_async16(sB + so, B + (size_t)(bn + r) * K + k0 + c * 4);
        }
        CP_COMMIT();
    };
    (void)fr;

    const int NK = K >> 5;
    fill(0, 0);
    fill(1, 1);

    for (int kc = 0; kc < NK; kc++) {
        const int buf = kc & 1;
        if (kc == NK - 1) { CP_WAIT0(); } else { CP_WAIT1(); }
        __syncthreads();

        const float* sA = smem + buf * BUF_F;
        const float* sB = sA + TILE_F;

        #pragma unroll
        for (int ks = 0; ks < 4; ks++) {
            const int kb = ks * 8 + tig;
            uint32_t af[4][4], bf[4][2];
            #pragma unroll
            for (int mt = 0; mt < 4; mt++) {
                const float* p = sA + (wm * 64 + mt * 16 + g) * PAD + kb;
                af[mt][0] = f2tf32(p[0]);
                af[mt][1] = f2tf32(p[8 * PAD]);
                af[mt][2] = f2tf32(p[4]);
                af[mt][3] = f2tf32(p[8 * PAD + 4]);
            }
            #pragma unroll
            for (int nt = 0; nt < 4; nt++) {
                const float* p = sB + (wn * 32 + nt * 8 + g) * PAD + kb;
                bf[nt][0] = f2tf32(p[0]);
                bf[nt][1] = f2tf32(p[4]);
            }
            #pragma unroll
            for (int mt = 0; mt < 4; mt++)
                #pragma unroll
                for (int nt = 0; nt < 4; nt++)
                    mma_tf32(acc[mt][nt], af[mt], bf[nt]);
        }
        __syncthreads();

        if (kc + 2 < NK) fill(buf, kc + 2);
    }

    // Epilogue: each thread owns rows {g, g+8} x cols {2*tig, 2*tig+1} per tile
    #pragma unroll
    for (int mt = 0; mt < 4; mt++) {
        const int row0 = bm + wm * 64 + mt * 16 + g;
        #pragma unroll
        for (int nt = 0; nt < 4; nt++) {
            const int col = bn + wn * 32 + nt * 8 + 2 * tig;
            const float b0 = bias[col], b1 = bias[col + 1];
            float2 o0, o1;
            o0.x = acc[mt][nt][0] + b0;  o0.y = acc[mt][nt][1] + b1;
            o1.x = acc[mt][nt][2] + b0;  o1.y = acc[mt][nt][3] + b1;
            *(float2*)(C + (size_t)row0 * N + col)       = o0;
            *(float2*)(C + (size_t)(row0 + 8) * N + col) = o1;
        }
    }
}

// ===========================================================================
// Fused causal attention (flash-style, fp32) — unchanged (passes, ~660us).
// ===========================================================================
__device__ __forceinline__ int SW(int r, int c4) {
    return r * 16 + (c4 ^ ((r >> 2) & 15));
}
__device__ __forceinline__ void fma4(float4& o, float a, const float4 v) {
    o.x += a * v.x; o.y += a * v.y; o.z += a * v.z; o.w += a * v.w;
}

__global__ __launch_bounds__(256) void attn_kernel(
    const float* __restrict__ qkv, float* __restrict__ ctx)
{
    __shared__ float4 Qs [64 * 16];
    __shared__ float4 KPs[64 * 16];   // K tile, then reused for P
    __shared__ float4 Vs [64 * 16];

    const int qt  = gridDim.x - 1 - blockIdx.x;   // heaviest tiles first
    const int bh  = blockIdx.y;
    const int b   = bh >> 4;
    const int h   = bh & 15;
    const int tid = threadIdx.x;
    const int ty  = tid >> 4;
    const int tx  = tid & 15;

    const float* base = qkv + (size_t)b * S_LEN * (3 * EMB);
    const int qoff = h * DH;
    const int koff = EMB + h * DH;
    const int voff = 2 * EMB + h * DH;

    #pragma unroll
    for (int i = 0; i < 4; i++) {
        const int idx = tid + 256 * i;
        const int r = idx >> 4, c4 = idx & 15;
        Qs[SW(r, c4)] = *(const float4*)(base + (size_t)(qt * 64 + r) * (3 * EMB) + qoff + c4 * 4);
    }

    const float scale = 0.125f;
    float  m[4], l[4];
    float4 oacc[4];
    #pragma unroll
    for (int r = 0; r < 4; r++) {
        m[r] = -1e30f; l[r] = 0.0f;
        oacc[r] = make_float4(0.f, 0.f, 0.f, 0.f);
    }

    for (int kt = 0; kt <= qt; kt++) {
        __syncthreads();

        #pragma unroll
        for (int i = 0; i < 4; i++) {
            const int idx = tid + 256 * i;
            const int r = idx >> 4, c4 = idx & 15;
            const float* rowp = base + (size_t)(kt * 64 + r) * (3 * EMB);
            KPs[SW(r, c4)] = *(const float4*)(rowp + koff + c4 * 4);
            Vs [SW(r, c4)] = *(const float4*)(rowp + voff + c4 * 4);
        }
        __syncthreads();

        float s[4][4];
        #pragma unroll
        for (int r = 0; r < 4; r++)
            #pragma unroll
            for (int c = 0; c < 4; c++)
                s[r][c] = 0.0f;

        #pragma unroll
        for (int k4 = 0; k4 < 16; k4++) {
            float4 q[4], kk[4];
            #pragma unroll
            for (int r = 0; r < 4; r++) q[r]  = Qs [SW(4 * ty + r, k4)];
            #pragma unroll
            for (int c = 0; c < 4; c++) kk[c] = KPs[SW(4 * tx + c, k4)];
            #pragma unroll
            for (int r = 0; r < 4; r++)
                #pragma unroll
                for (int c = 0; c < 4; c++)
                    s[r][c] += q[r].x * kk[c].x + q[r].y * kk[c].y
                             + q[r].z * kk[c].z + q[r].w * kk[c].w;
        }

        #pragma unroll
        for (int r = 0; r < 4; r++)
            #pragma unroll
            for (int c = 0; c < 4; c++) {
                s[r][c] *= scale;
                if (kt == qt && (4 * tx + c) > (4 * ty + r)) s[r][c] = -1e30f;
            }

        float mt[4];
        #pragma unroll
        for (int r = 0; r < 4; r++) {
            mt[r] = fmaxf(fmaxf(s[r][0], s[r][1]), fmaxf(s[r][2], s[r][3]));
            #pragma unroll
            for (int o = 8; o > 0; o >>= 1)
                mt[r] = fmaxf(mt[r], __shfl_xor_sync(0xffffffffu, mt[r], o));
        }

        float p[4][4];
        #pragma unroll
        for (int r = 0; r < 4; r++) {
            const float mnew = fmaxf(m[r], mt[r]);
            const float corr = __expf(m[r] - mnew);
            float rs = 0.0f;
            #pragma unroll
            for (int c = 0; c < 4; c++) {
                p[r][c] = __expf(s[r][c] - mnew);
                rs += p[r][c];
            }
            #pragma unroll
            for (int o = 8; o > 0; o >>= 1)
                rs += __shfl_xor_sync(0xffffffffu, rs, o);
            l[r] = l[r] * corr + rs;
            m[r] = mnew;
            oacc[r].x *= corr; oacc[r].y *= corr; oacc[r].z *= corr; oacc[r].w *= corr;
        }

        __syncthreads();
        #pragma unroll
        for (int r = 0; r < 4; r++)
            KPs[SW(4 * ty + r, tx)] = make_float4(p[r][0], p[r][1], p[r][2], p[r][3]);
        __syncthreads();

        #pragma unroll
        for (int k4 = 0; k4 < 16; k4++) {
            float4 pv[4];
            #pragma unroll
            for (int r = 0; r < 4; r++) pv[r] = KPs[SW(4 * ty + r, k4)];
            const float4 v0 = Vs[SW(4 * k4 + 0, tx)];
            const float4 v1 = Vs[SW(4 * k4 + 1, tx)];
            const float4 v2 = Vs[SW(4 * k4 + 2, tx)];
            const float4 v3 = Vs[SW(4 * k4 + 3, tx)];
            #pragma unroll
            for (int r = 0; r < 4; r++) {
                fma4(oacc[r], pv[r].x, v0);
                fma4(oacc[r], pv[r].y, v1);
                fma4(oacc[r], pv[r].z, v2);
                fma4(oacc[r], pv[r].w, v3);
            }
        }
    }

    #pragma unroll
    for (int r = 0; r < 4; r++) {
        const float inv = 1.0f / l[r];
        float4 o = oacc[r];
        o.x *= inv; o.y *= inv; o.z *= inv; o.w *= inv;
        const size_t row = (size_t)b * S_LEN + qt * 64 + 4 * ty + r;
        *(float4*)&ctx[row * EMB + h * DH + 4 * tx] = o;
    }
}

// ===========================================================================
// Launch: tf32 mma qkv-proj -> fused attention -> tf32 mma out-proj
// ===========================================================================
extern "C" void kernel_launch(void* const* d_in, const int* in_sizes, int n_in,
                              void* d_out, int out_size)
{
    const float* x     = (const float*)d_in[0];
    const float* w_in  = (const float*)d_in[1];
    const float* b_in  = (const float*)d_in[2];
    const float* w_out = (const float*)d_in[3];
    const float* b_out = (const float*)d_in[4];
    float* out = (float*)d_out;

    float *qkv = nullptr, *ctx = nullptr;
    cudaGetSymbolAddress((void**)&qkv, g_qkv);
    cudaGetSymbolAddress((void**)&ctx, g_ctx);

    const int M = BATCH * S_LEN;   // 4096

    static bool attr_set = false;
    if (!attr_set) {
        cudaFuncSetAttribute(gemm_mma,
                             cudaFuncAttributeMaxDynamicSharedMemorySize, GM_SMEM);
        attr_set = true;
    }

    // 1) qkv = x @ in_proj_w^T + in_proj_b   [4096, 3072]
    gemm_mma<<<dim3((3 * EMB) / 128, M / 128), 256, GM_SMEM>>>(
        x, w_in, b_in, qkv, M, 3 * EMB, EMB);

    // 2) fused causal attention -> ctx [4096, 1024]
    attn_kernel<<<dim3(S_LEN / 64, BATCH * HEADS), 256>>>(qkv, ctx);

    // 3) out = ctx @ out_proj_w^T + out_proj_b   [4096, 1024]
    gemm_mma<<<dim3(EMB / 128, M / 128), 256, GM_SMEM>>>(
        ctx, w_out, b_out, out, M, EMB, EMB);
}

// round 6
// speedup vs baseline: 2.0407x; 1.2686x over previous
#include <cuda_runtime.h>
#include <cstdint>

// Problem constants
#define S_LEN 2048
#define EMB   1024
#define HEADS 16
#define DH    64
#define BATCH 2

// Scratch (no allocations allowed): qkv = [B,S,3E], ctx = [B,S,E]
__device__ float g_qkv[(size_t)BATCH * S_LEN * 3 * EMB];
__device__ float g_ctx[(size_t)BATCH * S_LEN * EMB];

// ===========================================================================
// Helpers
// ===========================================================================
__device__ __forceinline__ uint32_t smem_u32(const void* p) {
    uint32_t a;
    asm("{ .reg .u64 t; cvta.to.shared.u64 t, %1; cvt.u32.u64 %0, t; }"
        : "=r"(a) : "l"(p));
    return a;
}

__device__ __forceinline__ void cp_async16(uint32_t dst, const void* src) {
    asm volatile("cp.async.cg.shared.global [%0], [%1], 16;"
                 :: "r"(dst), "l"(src));
}
#define CP_COMMIT() asm volatile("cp.async.commit_group;")
#define CP_WAIT1()  asm volatile("cp.async.wait_group 1;")
#define CP_WAIT0()  asm volatile("cp.async.wait_group 0;")

__device__ __forceinline__ uint32_t f2tf32(float f) {
    uint32_t r;
    asm("cvt.rna.tf32.f32 %0, %1;" : "=r"(r) : "f"(f));
    return r;
}

// Split fp32 into tf32 hi + tf32 lo (3xTF32 error compensation)
__device__ __forceinline__ void tf32_split(float x, uint32_t& hi, uint32_t& lo) {
    hi = f2tf32(x);
    lo = f2tf32(x - __uint_as_float(hi));
}

// mma.sync m16n8k8 tf32: D += A*B, fp32 accumulate
__device__ __forceinline__ void mma_tf32(
    float* c, const uint32_t* a, const uint32_t* b)
{
    asm volatile(
        "mma.sync.aligned.m16n8k8.row.col.f32.tf32.tf32.f32 "
        "{%0,%1,%2,%3}, {%4,%5,%6,%7}, {%8,%9}, {%0,%1,%2,%3};"
        : "+f"(c[0]), "+f"(c[1]), "+f"(c[2]), "+f"(c[3])
        : "r"(a[0]), "r"(a[1]), "r"(a[2]), "r"(a[3]), "r"(b[0]), "r"(b[1]));
}

// ===========================================================================
// tf32 tensor-core GEMM:  C[M,N] = A[M,K] @ B[N,K]^T + bias[N]  (unchanged)
// ===========================================================================
#define PAD     36
#define TILE_F  (128 * PAD)
#define BUF_F   (2 * TILE_F)
#define GM_SMEM (2 * BUF_F * 4)

__global__ __launch_bounds__(256) void gemm_mma(
    const float* __restrict__ A, const float* __restrict__ B,
    const float* __restrict__ bias, float* __restrict__ C,
    int M, int N, int K)
{
    extern __shared__ float smem[];
    const int tid  = threadIdx.x;
    const int wid  = tid >> 5;
    const int lane = tid & 31;
    const int wm   = wid >> 2;
    const int wn   = wid & 3;
    const int g    = lane >> 2;
    const int tig  = lane & 3;
    const int bm   = blockIdx.y * 128;
    const int bn   = blockIdx.x * 128;

    float acc[4][4][4];
    #pragma unroll
    for (int mt = 0; mt < 4; mt++)
        #pragma unroll
        for (int nt = 0; nt < 4; nt++)
            #pragma unroll
            for (int i = 0; i < 4; i++)
                acc[mt][nt][i] = 0.0f;

    auto fill = [&](int buf, int kc) {
        const int k0 = kc << 5;
        const uint32_t sA = smem_u32(smem + buf * BUF_F);
        const uint32_t sB = sA + TILE_F * 4;
        #pragma unroll
        for (int i = 0; i < 4; i++) {
            const int id = tid + (i << 8);
            const int r  = id >> 3;
            const int c  = id & 7;
            const uint32_t so = (uint32_t)(r * PAD + c * 4) * 4;
            cp_async16(sA + so, A + (size_t)(bm + r) * K + k0 + c * 4);
            cp_async16(sB + so, B + (size_t)(bn + r) * K + k0 + c * 4);
        }
        CP_COMMIT();
    };

    const int NK = K >> 5;
    fill(0, 0);
    fill(1, 1);

    for (int kc = 0; kc < NK; kc++) {
        const int buf = kc & 1;
        if (kc == NK - 1) { CP_WAIT0(); } else { CP_WAIT1(); }
        __syncthreads();

        const float* sA = smem + buf * BUF_F;
        const float* sB = sA + TILE_F;

        #pragma unroll
        for (int ks = 0; ks < 4; ks++) {
            const int kb = ks * 8 + tig;
            uint32_t af[4][4], bf[4][2];
            #pragma unroll
            for (int mt = 0; mt < 4; mt++) {
                const float* p = sA + (wm * 64 + mt * 16 + g) * PAD + kb;
                af[mt][0] = f2tf32(p[0]);
                af[mt][1] = f2tf32(p[8 * PAD]);
                af[mt][2] = f2tf32(p[4]);
                af[mt][3] = f2tf32(p[8 * PAD + 4]);
            }
            #pragma unroll
            for (int nt = 0; nt < 4; nt++) {
                const float* p = sB + (wn * 32 + nt * 8 + g) * PAD + kb;
                bf[nt][0] = f2tf32(p[0]);
                bf[nt][1] = f2tf32(p[4]);
            }
            #pragma unroll
            for (int mt = 0; mt < 4; mt++)
                #pragma unroll
                for (int nt = 0; nt < 4; nt++)
                    mma_tf32(acc[mt][nt], af[mt], bf[nt]);
        }
        __syncthreads();

        if (kc + 2 < NK) fill(buf, kc + 2);
    }

    #pragma unroll
    for (int mt = 0; mt < 4; mt++) {
        const int row0 = bm + wm * 64 + mt * 16 + g;
        #pragma unroll
        for (int nt = 0; nt < 4; nt++) {
            const int col = bn + wn * 32 + nt * 8 + 2 * tig;
            const float b0 = bias[col], b1 = bias[col + 1];
            float2 o0, o1;
            o0.x = acc[mt][nt][0] + b0;  o0.y = acc[mt][nt][1] + b1;
            o1.x = acc[mt][nt][2] + b0;  o1.y = acc[mt][nt][3] + b1;
            *(float2*)(C + (size_t)row0 * N + col)       = o0;
            *(float2*)(C + (size_t)(row0 + 8) * N + col) = o1;
        }
    }
}

// ===========================================================================
// Tensor-core flash attention with 3xTF32 error compensation.
// CTA: 128 queries x one (b,h); 8 warps, 16 q-rows each. Key tiles of 64.
// QK^T:  S += Qhi*Khi + Qhi*Klo + Qlo*Khi   (near-fp32 accurate)
// PV:    O += Phi*Vhi + Plo*Vhi + Phi*Vlo   (P from exact fp32 exp)
// PV A-operand comes straight from the S accumulator via the k-permutation
// (aP = {c0,c2,c1,c3}, V b-frags from rows {2t,2t+1}).
// K/V tiles double-buffered with cp.async; smem rows padded to 68 floats.
// ===========================================================================
#define AP        68                           // padded row (floats)
#define QT_F      (128 * AP)                   // 8704 floats
#define KVT_F     (64 * AP)                    // 4352 floats
#define A_KOFF    QT_F
#define A_VOFF    (QT_F + 2 * KVT_F)
#define ATT_SMEM  ((QT_F + 4 * KVT_F) * 4)     // 104448 bytes

__global__ __launch_bounds__(256) void attn_mma_kernel(
    const float* __restrict__ qkv, float* __restrict__ ctx)
{
    extern __shared__ float smem[];
    const int tid  = threadIdx.x;
    const int w    = tid >> 5;
    const int lane = tid & 31;
    const int g    = lane >> 2;
    const int tig  = lane & 3;

    const int qt = gridDim.x - 1 - blockIdx.x;     // heaviest tiles first
    const int bh = blockIdx.y;
    const int b  = bh >> 4;
    const int h  = bh & 15;

    const float* base = qkv + (size_t)b * S_LEN * (3 * EMB);
    const int ktmax = 2 * qt + 1;

    // ---- issue Q stage (group bundled with first KV fill) ----
    {
        const float* Qsrc = base + (size_t)(qt * 128) * (3 * EMB) + h * DH;
        const uint32_t qs = smem_u32(smem);
        #pragma unroll
        for (int i = 0; i < 8; i++) {
            const int id = tid + (i << 8);
            const int r = id >> 4, c4 = id & 15;
            cp_async16(qs + (uint32_t)((r * AP + c4 * 4) * 4),
                       Qsrc + (size_t)r * (3 * EMB) + c4 * 4);
        }
    }

    auto fill_kv = [&](int buf, int kt) {
        const float* Ksrc = base + (size_t)(kt * 64) * (3 * EMB) + EMB + h * DH;
        const float* Vsrc = Ksrc + EMB;
        const uint32_t kd = smem_u32(smem + A_KOFF + buf * KVT_F);
        const uint32_t vd = smem_u32(smem + A_VOFF + buf * KVT_F);
        #pragma unroll
        for (int i = 0; i < 4; i++) {
            const int id = tid + (i << 8);
            const int r = id >> 4, c4 = id & 15;
            const uint32_t so = (uint32_t)((r * AP + c4 * 4) * 4);
            const size_t go = (size_t)r * (3 * EMB) + c4 * 4;
            cp_async16(kd + so, Ksrc + go);
            cp_async16(vd + so, Vsrc + go);
        }
        CP_COMMIT();
    };

    fill_kv(0, 0);          // group: Q + KV(0)
    fill_kv(1, 1);          // ktmax >= 1 always

    uint32_t Qh[8][4], Ql[8][4];
    float S[8][4];
    float O[8][4];
    float m0 = -1e30f, m1 = -1e30f, l0 = 0.0f, l1 = 0.0f;
    #pragma unroll
    for (int nt = 0; nt < 8; nt++)
        #pragma unroll
        for (int i = 0; i < 4; i++)
            O[nt][i] = 0.0f;

    for (int kt = 0; kt <= ktmax; kt++) {
        if (kt < ktmax) { CP_WAIT1(); } else { CP_WAIT0(); }
        __syncthreads();

        if (kt == 0) {   // Q fragments, split into tf32 hi/lo once
            const float* Qp = smem + (16 * w + g) * AP + tig;
            #pragma unroll
            for (int kb = 0; kb < 8; kb++) {
                tf32_split(Qp[kb * 8],              Qh[kb][0], Ql[kb][0]);
                tf32_split(Qp[8 * AP + kb * 8],     Qh[kb][1], Ql[kb][1]);
                tf32_split(Qp[kb * 8 + 4],          Qh[kb][2], Ql[kb][2]);
                tf32_split(Qp[8 * AP + kb * 8 + 4], Qh[kb][3], Ql[kb][3]);
            }
        }

        const int buf = kt & 1;
        const float* Kl = smem + A_KOFF + buf * KVT_F + g * AP + tig;
        const float* Vl = smem + A_VOFF + buf * KVT_F + 2 * tig * AP + g;

        // ---- S = Q K^T (3xTF32) ----
        #pragma unroll
        for (int nt = 0; nt < 8; nt++)
            #pragma unroll
            for (int i = 0; i < 4; i++)
                S[nt][i] = 0.0f;

        #pragma unroll
        for (int kb = 0; kb < 8; kb++) {
            #pragma unroll
            for (int nt = 0; nt < 8; nt++) {
                uint32_t bh_[2], bl_[2];
                tf32_split(Kl[nt * (8 * AP) + kb * 8],     bh_[0], bl_[0]);
                tf32_split(Kl[nt * (8 * AP) + kb * 8 + 4], bh_[1], bl_[1]);
                mma_tf32(S[nt], Qh[kb], bh_);
                mma_tf32(S[nt], Qh[kb], bl_);
                mma_tf32(S[nt], Ql[kb], bh_);
            }
        }

        // ---- causal mask (diagonal region only) ----
        if (kt >= 2 * qt) {
            const int q0 = 16 * w + g;
            const int q1 = q0 + 8;
            const int kb0 = (kt - 2 * qt) * 64;
            #pragma unroll
            for (int nt = 0; nt < 8; nt++) {
                const int kc = kb0 + nt * 8 + 2 * tig;
                if (kc     > q0) S[nt][0] = -1e30f;
                if (kc + 1 > q0) S[nt][1] = -1e30f;
                if (kc     > q1) S[nt][2] = -1e30f;
                if (kc + 1 > q1) S[nt][3] = -1e30f;
            }
        }

        // ---- online softmax (scale 0.125 folded into exp) ----
        float t0 = -1e30f, t1 = -1e30f;
        #pragma unroll
        for (int nt = 0; nt < 8; nt++) {
            t0 = fmaxf(t0, fmaxf(S[nt][0], S[nt][1]));
            t1 = fmaxf(t1, fmaxf(S[nt][2], S[nt][3]));
        }
        #pragma unroll
        for (int o = 1; o <= 2; o <<= 1) {
            t0 = fmaxf(t0, __shfl_xor_sync(0xffffffffu, t0, o));
            t1 = fmaxf(t1, __shfl_xor_sync(0xffffffffu, t1, o));
        }
        const float mn0 = fmaxf(m0, t0), mn1 = fmaxf(m1, t1);
        const float c0 = __expf(0.125f * (m0 - mn0));
        const float c1 = __expf(0.125f * (m1 - mn1));
        m0 = mn0; m1 = mn1;

        float rs0 = 0.0f, rs1 = 0.0f;
        #pragma unroll
        for (int nt = 0; nt < 8; nt++) {
            S[nt][0] = __expf(0.125f * (S[nt][0] - mn0));
            S[nt][1] = __expf(0.125f * (S[nt][1] - mn0));
            S[nt][2] = __expf(0.125f * (S[nt][2] - mn1));
            S[nt][3] = __expf(0.125f * (S[nt][3] - mn1));
            rs0 += S[nt][0] + S[nt][1];
            rs1 += S[nt][2] + S[nt][3];
        }
        #pragma unroll
        for (int o = 1; o <= 2; o <<= 1) {
            rs0 += __shfl_xor_sync(0xffffffffu, rs0, o);
            rs1 += __shfl_xor_sync(0xffffffffu, rs1, o);
        }
        l0 = l0 * c0 + rs0;
        l1 = l1 * c1 + rs1;

        #pragma unroll
        for (int nt = 0; nt < 8; nt++) {
            O[nt][0] *= c0; O[nt][1] *= c0;
            O[nt][2] *= c1; O[nt][3] *= c1;
        }

        // ---- O += P V (3-term compensated; k-permuted layout) ----
        #pragma unroll
        for (int kb = 0; kb < 8; kb++) {
            uint32_t aPh[4], aPl[4];
            tf32_split(S[kb][0], aPh[0], aPl[0]);
            tf32_split(S[kb][2], aPh[1], aPl[1]);
            tf32_split(S[kb][1], aPh[2], aPl[2]);
            tf32_split(S[kb][3], aPh[3], aPl[3]);
            #pragma unroll
            for (int nt = 0; nt < 8; nt++) {
                uint32_t bh_[2], bl_[2];
                tf32_split(Vl[kb * (8 * AP) + nt * 8],      bh_[0], bl_[0]);
                tf32_split(Vl[kb * (8 * AP) + nt * 8 + AP], bh_[1], bl_[1]);
                mma_tf32(O[nt], aPh, bh_);
                mma_tf32(O[nt], aPl, bh_);
                mma_tf32(O[nt], aPh, bl_);
            }
        }

        __syncthreads();   // all readers done before refill of this buffer
        if (kt + 2 <= ktmax) fill_kv(buf, kt + 2);
    }

    // ---- normalize + write ctx ----
    const float i0 = 1.0f / l0, i1 = 1.0f / l1;
    const size_t row0 = (size_t)b * S_LEN + qt * 128 + 16 * w + g;
    #pragma unroll
    for (int nt = 0; nt < 8; nt++) {
        const int col = h * DH + nt * 8 + 2 * tig;
        float2 o0, o1;
        o0.x = O[nt][0] * i0;  o0.y = O[nt][1] * i0;
        o1.x = O[nt][2] * i1;  o1.y = O[nt][3] * i1;
        *(float2*)(ctx + row0 * EMB + col)       = o0;
        *(float2*)(ctx + (row0 + 8) * EMB + col) = o1;
    }
}

// ===========================================================================
// Launch
// ===========================================================================
extern "C" void kernel_launch(void* const* d_in, const int* in_sizes, int n_in,
                              void* d_out, int out_size)
{
    const float* x     = (const float*)d_in[0];
    const float* w_in  = (const float*)d_in[1];
    const float* b_in  = (const float*)d_in[2];
    const float* w_out = (const float*)d_in[3];
    const float* b_out = (const float*)d_in[4];
    float* out = (float*)d_out;

    float *qkv = nullptr, *ctx = nullptr;
    cudaGetSymbolAddress((void**)&qkv, g_qkv);
    cudaGetSymbolAddress((void**)&ctx, g_ctx);

    const int M = BATCH * S_LEN;   // 4096

    static bool attr_set = false;
    if (!attr_set) {
        cudaFuncSetAttribute(gemm_mma,
                             cudaFuncAttributeMaxDynamicSharedMemorySize, GM_SMEM);
        cudaFuncSetAttribute(attn_mma_kernel,
                             cudaFuncAttributeMaxDynamicSharedMemorySize, ATT_SMEM);
        attr_set = true;
    }

    // 1) qkv = x @ in_proj_w^T + in_proj_b   [4096, 3072]
    gemm_mma<<<dim3((3 * EMB) / 128, M / 128), 256, GM_SMEM>>>(
        x, w_in, b_in, qkv, M, 3 * EMB, EMB);

    // 2) fused causal attention -> ctx [4096, 1024]
    attn_mma_kernel<<<dim3(S_LEN / 128, BATCH * HEADS), 256, ATT_SMEM>>>(qkv, ctx);

    // 3) out = ctx @ out_proj_w^T + out_proj_b   [4096, 1024]
    gemm_mma<<<dim3(EMB / 128, M / 128), 256, GM_SMEM>>>(
        ctx, w_out, b_out, out, M, EMB, EMB);
}

// round 7
// speedup vs baseline: 2.3839x; 1.1682x over previous
#include <cuda_runtime.h>
#include <cstdint>

// Problem constants
#define S_LEN 2048
#define EMB   1024
#define HEADS 16
#define DH    64
#define BATCH 2

// Scratch (no allocations allowed)
__device__ float g_qkv[(size_t)BATCH * S_LEN * 3 * EMB];   // [B,S,3E]
__device__ float g_ctx[(size_t)BATCH * S_LEN * EMB];       // [B,S,E] (tf32-rounded)
__device__ float g_xr [(size_t)BATCH * S_LEN * EMB];       // rounded x
__device__ float g_wir[(size_t)3 * EMB * EMB];             // rounded in_proj_w
__device__ float g_wor[(size_t)EMB * EMB];                 // rounded out_proj_w

// ===========================================================================
// Helpers
// ===========================================================================
__device__ __forceinline__ uint32_t smem_u32(const void* p) {
    uint32_t a;
    asm("{ .reg .u64 t; cvta.to.shared.u64 t, %1; cvt.u32.u64 %0, t; }"
        : "=r"(a) : "l"(p));
    return a;
}

__device__ __forceinline__ void cp_async16(uint32_t dst, const void* src) {
    asm volatile("cp.async.cg.shared.global [%0], [%1], 16;"
                 :: "r"(dst), "l"(src));
}
#define CP_COMMIT() asm volatile("cp.async.commit_group;")
#define CP_WAIT1()  asm volatile("cp.async.wait_group 1;")
#define CP_WAIT0()  asm volatile("cp.async.wait_group 0;")

__device__ __forceinline__ uint32_t f2tf32(float f) {
    uint32_t r;
    asm("cvt.rna.tf32.f32 %0, %1;" : "=r"(r) : "f"(f));
    return r;
}
__device__ __forceinline__ float rnd_tf32(float f) {
    return __uint_as_float(f2tf32(f));
}

// Split fp32 into tf32 hi + tf32 lo (3xTF32 error compensation)
__device__ __forceinline__ void tf32_split(float x, uint32_t& hi, uint32_t& lo) {
    hi = f2tf32(x);
    lo = f2tf32(x - __uint_as_float(hi));
}

// mma.sync m16n8k8 tf32: D += A*B, fp32 accumulate
__device__ __forceinline__ void mma_tf32(
    float* c, const uint32_t* a, const uint32_t* b)
{
    asm volatile(
        "mma.sync.aligned.m16n8k8.row.col.f32.tf32.tf32.f32 "
        "{%0,%1,%2,%3}, {%4,%5,%6,%7}, {%8,%9}, {%0,%1,%2,%3};"
        : "+f"(c[0]), "+f"(c[1]), "+f"(c[2]), "+f"(c[3])
        : "r"(a[0]), "r"(a[1]), "r"(a[2]), "r"(a[3]), "r"(b[0]), "r"(b[1]));
}

// ===========================================================================
// Elementwise tf32 pre-rounding (RNA). Idempotent; feeds GEMMs raw bits.
// ===========================================================================
__global__ __launch_bounds__(256) void round_tf32_kernel(
    const float4* __restrict__ src, float4* __restrict__ dst, int n4)
{
    for (int i = blockIdx.x * 256 + threadIdx.x; i < n4; i += gridDim.x * 256) {
        float4 v = src[i];
        v.x = rnd_tf32(v.x); v.y = rnd_tf32(v.y);
        v.z = rnd_tf32(v.z); v.w = rnd_tf32(v.w);
        dst[i] = v;
    }
}

// ===========================================================================
// tf32 tensor-core GEMM on PRE-ROUNDED inputs:
//   C[M,N] = A[M,K] @ B[N,K]^T + bias[N]
// No in-loop cvt: operands are already tf32 values; HW truncation is a no-op.
// ===========================================================================
#define PAD     36
#define TILE_F  (128 * PAD)
#define BUF_F   (2 * TILE_F)
#define GM_SMEM (2 * BUF_F * 4)

__global__ __launch_bounds__(256, 2) void gemm_mma(
    const float* __restrict__ A, const float* __restrict__ B,
    const float* __restrict__ bias, float* __restrict__ C,
    int M, int N, int K)
{
    extern __shared__ float smem[];
    const int tid  = threadIdx.x;
    const int wid  = tid >> 5;
    const int lane = tid & 31;
    const int wm   = wid >> 2;
    const int wn   = wid & 3;
    const int g    = lane >> 2;
    const int tig  = lane & 3;
    const int bm   = blockIdx.y * 128;
    const int bn   = blockIdx.x * 128;

    float acc[4][4][4];
    #pragma unroll
    for (int mt = 0; mt < 4; mt++)
        #pragma unroll
        for (int nt = 0; nt < 4; nt++)
            #pragma unroll
            for (int i = 0; i < 4; i++)
                acc[mt][nt][i] = 0.0f;

    auto fill = [&](int buf, int kc) {
        const int k0 = kc << 5;
        const uint32_t sA = smem_u32(smem + buf * BUF_F);
        const uint32_t sB = sA + TILE_F * 4;
        #pragma unroll
        for (int i = 0; i < 4; i++) {
            const int id = tid + (i << 8);
            const int r  = id >> 3;
            const int c  = id & 7;
            const uint32_t so = (uint32_t)(r * PAD + c * 4) * 4;
            cp_async16(sA + so, A + (size_t)(bm + r) * K + k0 + c * 4);
            cp_async16(sB + so, B + (size_t)(bn + r) * K + k0 + c * 4);
        }
        CP_COMMIT();
    };

    const int NK = K >> 5;
    fill(0, 0);
    fill(1, 1);

    for (int kc = 0; kc < NK; kc++) {
        const int buf = kc & 1;
        if (kc == NK - 1) { CP_WAIT0(); } else { CP_WAIT1(); }
        __syncthreads();

        const float* sA = smem + buf * BUF_F;
        const float* sB = sA + TILE_F;

        #pragma unroll
        for (int ks = 0; ks < 4; ks++) {
            const int kb = ks * 8 + tig;
            uint32_t af[4][4], bf[4][2];
            #pragma unroll
            for (int mt = 0; mt < 4; mt++) {
                const float* p = sA + (wm * 64 + mt * 16 + g) * PAD + kb;
                af[mt][0] = __float_as_uint(p[0]);
                af[mt][1] = __float_as_uint(p[8 * PAD]);
                af[mt][2] = __float_as_uint(p[4]);
                af[mt][3] = __float_as_uint(p[8 * PAD + 4]);
            }
            #pragma unroll
            for (int nt = 0; nt < 4; nt++) {
                const float* p = sB + (wn * 32 + nt * 8 + g) * PAD + kb;
                bf[nt][0] = __float_as_uint(p[0]);
                bf[nt][1] = __float_as_uint(p[4]);
            }
            #pragma unroll
            for (int mt = 0; mt < 4; mt++)
                #pragma unroll
                for (int nt = 0; nt < 4; nt++)
                    mma_tf32(acc[mt][nt], af[mt], bf[nt]);
        }
        __syncthreads();

        if (kc + 2 < NK) fill(buf, kc + 2);
    }

    #pragma unroll
    for (int mt = 0; mt < 4; mt++) {
        const int row0 = bm + wm * 64 + mt * 16 + g;
        #pragma unroll
        for (int nt = 0; nt < 4; nt++) {
            const int col = bn + wn * 32 + nt * 8 + 2 * tig;
            const float b0 = bias[col], b1 = bias[col + 1];
            float2 o0, o1;
            o0.x = acc[mt][nt][0] + b0;  o0.y = acc[mt][nt][1] + b1;
            o1.x = acc[mt][nt][2] + b0;  o1.y = acc[mt][nt][3] + b1;
            *(float2*)(C + (size_t)row0 * N + col)       = o0;
            *(float2*)(C + (size_t)(row0 + 8) * N + col) = o1;
        }
    }
}

// ===========================================================================
// Tensor-core flash attention, 3xTF32 compensated, with K/V pre-split in smem.
// CTA: 128 queries x one (b,h); 8 warps, 16 q-rows each. Key tiles of 64.
// After each K/V tile lands (cp.async), a convert pass splits it IN PLACE into
// hi/lo tf32 arrays once per CTA (was: every warp re-splitting redundantly).
// Mainloop is then pure LDS + mma: QK^T and PV each 3 compensated mmas.
// PV A-operand from the S accumulator via the k-permutation
// (aP = {c0,c2,c1,c3}, V b-frags from rows {2t,2t+1}).
// ===========================================================================
#define AP        68                            // padded row (floats)
#define QT_F      (128 * AP)                    // 8704 floats
#define KVT_F     (64 * AP)                     // 4352 floats
#define A_KHI     QT_F
#define A_KLO     (QT_F + 2 * KVT_F)
#define A_VHI     (QT_F + 4 * KVT_F)
#define A_VLO     (QT_F + 6 * KVT_F)
#define ATT_SMEM  ((QT_F + 8 * KVT_F) * 4)      // 174080 bytes

__global__ __launch_bounds__(256) void attn_mma_kernel(
    const float* __restrict__ qkv, float* __restrict__ ctx)
{
    extern __shared__ float smem[];
    const int tid  = threadIdx.x;
    const int w    = tid >> 5;
    const int lane = tid & 31;
    const int g    = lane >> 2;
    const int tig  = lane & 3;

    const int qt = gridDim.x - 1 - blockIdx.x;     // heaviest tiles first
    const int bh = blockIdx.y;
    const int b  = bh >> 4;
    const int h  = bh & 15;

    const float* base = qkv + (size_t)b * S_LEN * (3 * EMB);
    const int ktmax = 2 * qt + 1;

    // ---- issue Q stage (group bundled with first KV fill) ----
    {
        const float* Qsrc = base + (size_t)(qt * 128) * (3 * EMB) + h * DH;
        const uint32_t qs = smem_u32(smem);
        #pragma unroll
        for (int i = 0; i < 8; i++) {
            const int id = tid + (i << 8);
            const int r = id >> 4, c4 = id & 15;
            cp_async16(qs + (uint32_t)((r * AP + c4 * 4) * 4),
                       Qsrc + (size_t)r * (3 * EMB) + c4 * 4);
        }
    }

    auto fill_kv = [&](int buf, int kt) {
        const float* Ksrc = base + (size_t)(kt * 64) * (3 * EMB) + EMB + h * DH;
        const float* Vsrc = Ksrc + EMB;
        const uint32_t kd = smem_u32(smem + A_KHI + buf * KVT_F);
        const uint32_t vd = smem_u32(smem + A_VHI + buf * KVT_F);
        #pragma unroll
        for (int i = 0; i < 4; i++) {
            const int id = tid + (i << 8);
            const int r = id >> 4, c4 = id & 15;
            const uint32_t so = (uint32_t)((r * AP + c4 * 4) * 4);
            const size_t go = (size_t)r * (3 * EMB) + c4 * 4;
            cp_async16(kd + so, Ksrc + go);
            cp_async16(vd + so, Vsrc + go);
        }
        CP_COMMIT();
    };

    fill_kv(0, 0);          // group: Q + KV(0)
    fill_kv(1, 1);          // ktmax >= 1 always

    uint32_t Qh[8][4], Ql[8][4];
    float S[8][4];
    float O[8][4];
    float m0 = -1e30f, m1 = -1e30f, l0 = 0.0f, l1 = 0.0f;
    #pragma unroll
    for (int nt = 0; nt < 8; nt++)
        #pragma unroll
        for (int i = 0; i < 4; i++)
            O[nt][i] = 0.0f;

    for (int kt = 0; kt <= ktmax; kt++) {
        if (kt < ktmax) { CP_WAIT1(); } else { CP_WAIT0(); }
        __syncthreads();

        const int buf = kt & 1;

        // ---- convert pass: split this tile's K/V into hi/lo, in place ----
        {
            float* Khi = smem + A_KHI + buf * KVT_F;
            float* Klo = smem + A_KLO + buf * KVT_F;
            float* Vhi = smem + A_VHI + buf * KVT_F;
            float* Vlo = smem + A_VLO + buf * KVT_F;
            #pragma unroll
            for (int i = 0; i < 4; i++) {
                const int id = tid + (i << 8);
                const int off = (id >> 4) * AP + (id & 15) * 4;
                float4 kx = *(float4*)(Khi + off);
                float4 vx = *(float4*)(Vhi + off);
                float4 kh, kl, vh, vl;
                kh.x = rnd_tf32(kx.x); kl.x = rnd_tf32(kx.x - kh.x);
                kh.y = rnd_tf32(kx.y); kl.y = rnd_tf32(kx.y - kh.y);
                kh.z = rnd_tf32(kx.z); kl.z = rnd_tf32(kx.z - kh.z);
                kh.w = rnd_tf32(kx.w); kl.w = rnd_tf32(kx.w - kh.w);
                vh.x = rnd_tf32(vx.x); vl.x = rnd_tf32(vx.x - vh.x);
                vh.y = rnd_tf32(vx.y); vl.y = rnd_tf32(vx.y - vh.y);
                vh.z = rnd_tf32(vx.z); vl.z = rnd_tf32(vx.z - vh.z);
                vh.w = rnd_tf32(vx.w); vl.w = rnd_tf32(vx.w - vh.w);
                *(float4*)(Khi + off) = kh;  *(float4*)(Klo + off) = kl;
                *(float4*)(Vhi + off) = vh;  *(float4*)(Vlo + off) = vl;
            }
        }
        __syncthreads();

        if (kt == 0) {   // Q fragments, split into tf32 hi/lo once
            const float* Qp = smem + (16 * w + g) * AP + tig;
            #pragma unroll
            for (int kb = 0; kb < 8; kb++) {
                tf32_split(Qp[kb * 8],              Qh[kb][0], Ql[kb][0]);
                tf32_split(Qp[8 * AP + kb * 8],     Qh[kb][1], Ql[kb][1]);
                tf32_split(Qp[kb * 8 + 4],          Qh[kb][2], Ql[kb][2]);
                tf32_split(Qp[8 * AP + kb * 8 + 4], Qh[kb][3], Ql[kb][3]);
            }
        }

        const float* Khl = smem + A_KHI + buf * KVT_F + g * AP + tig;
        const float* Kll = smem + A_KLO + buf * KVT_F + g * AP + tig;
        const float* Vhl = smem + A_VHI + buf * KVT_F + 2 * tig * AP + g;
        const float* Vll = smem + A_VLO + buf * KVT_F + 2 * tig * AP + g;

        // ---- S = Q K^T (3xTF32) ----
        #pragma unroll
        for (int nt = 0; nt < 8; nt++)
            #pragma unroll
            for (int i = 0; i < 4; i++)
                S[nt][i] = 0.0f;

        #pragma unroll
        for (int kb = 0; kb < 8; kb++) {
            #pragma unroll
            for (int nt = 0; nt < 8; nt++) {
                const int so = nt * (8 * AP) + kb * 8;
                uint32_t bh_[2], bl_[2];
                bh_[0] = __float_as_uint(Khl[so]);
                bh_[1] = __float_as_uint(Khl[so + 4]);
                bl_[0] = __float_as_uint(Kll[so]);
                bl_[1] = __float_as_uint(Kll[so + 4]);
                mma_tf32(S[nt], Qh[kb], bh_);
                mma_tf32(S[nt], Qh[kb], bl_);
                mma_tf32(S[nt], Ql[kb], bh_);
            }
        }

        // ---- causal mask (diagonal region only) ----
        if (kt >= 2 * qt) {
            const int q0 = 16 * w + g;
            const int q1 = q0 + 8;
            const int kb0 = (kt - 2 * qt) * 64;
            #pragma unroll
            for (int nt = 0; nt < 8; nt++) {
                const int kc = kb0 + nt * 8 + 2 * tig;
                if (kc     > q0) S[nt][0] = -1e30f;
                if (kc + 1 > q0) S[nt][1] = -1e30f;
                if (kc     > q1) S[nt][2] = -1e30f;
                if (kc + 1 > q1) S[nt][3] = -1e30f;
            }
        }

        // ---- online softmax (scale 0.125 folded into exp) ----
        float t0 = -1e30f, t1 = -1e30f;
        #pragma unroll
        for (int nt = 0; nt < 8; nt++) {
            t0 = fmaxf(t0, fmaxf(S[nt][0], S[nt][1]));
            t1 = fmaxf(t1, fmaxf(S[nt][2], S[nt][3]));
        }
        #pragma unroll
        for (int o = 1; o <= 2; o <<= 1) {
            t0 = fmaxf(t0, __shfl_xor_sync(0xffffffffu, t0, o));
            t1 = fmaxf(t1, __shfl_xor_sync(0xffffffffu, t1, o));
        }
        const float mn0 = fmaxf(m0, t0), mn1 = fmaxf(m1, t1);
        const float c0 = __expf(0.125f * (m0 - mn0));
        const float c1 = __expf(0.125f * (m1 - mn1));
        m0 = mn0; m1 = mn1;

        float rs0 = 0.0f, rs1 = 0.0f;
        #pragma unroll
        for (int nt = 0; nt < 8; nt++) {
            S[nt][0] = __expf(0.125f * (S[nt][0] - mn0));
            S[nt][1] = __expf(0.125f * (S[nt][1] - mn0));
            S[nt][2] = __expf(0.125f * (S[nt][2] - mn1));
            S[nt][3] = __expf(0.125f * (S[nt][3] - mn1));
            rs0 += S[nt][0] + S[nt][1];
            rs1 += S[nt][2] + S[nt][3];
        }
        #pragma unroll
        for (int o = 1; o <= 2; o <<= 1) {
            rs0 += __shfl_xor_sync(0xffffffffu, rs0, o);
            rs1 += __shfl_xor_sync(0xffffffffu, rs1, o);
        }
        l0 = l0 * c0 + rs0;
        l1 = l1 * c1 + rs1;

        #pragma unroll
        for (int nt = 0; nt < 8; nt++) {
            O[nt][0] *= c0; O[nt][1] *= c0;
            O[nt][2] *= c1; O[nt][3] *= c1;
        }

        // ---- O += P V (3-term compensated; k-permuted layout) ----
        #pragma unroll
        for (int kb = 0; kb < 8; kb++) {
            uint32_t aPh[4], aPl[4];
            tf32_split(S[kb][0], aPh[0], aPl[0]);
            tf32_split(S[kb][2], aPh[1], aPl[1]);
            tf32_split(S[kb][1], aPh[2], aPl[2]);
            tf32_split(S[kb][3], aPh[3], aPl[3]);
            #pragma unroll
            for (int nt = 0; nt < 8; nt++) {
                const int so = kb * (8 * AP) + nt * 8;
                uint32_t bh_[2], bl_[2];
                bh_[0] = __float_as_uint(Vhl[so]);
                bh_[1] = __float_as_uint(Vhl[so + AP]);
                bl_[0] = __float_as_uint(Vll[so]);
                bl_[1] = __float_as_uint(Vll[so + AP]);
                mma_tf32(O[nt], aPh, bh_);
                mma_tf32(O[nt], aPl, bh_);
                mma_tf32(O[nt], aPh, bl_);
            }
        }

        __syncthreads();   // all readers done before refill of this buffer
        if (kt + 2 <= ktmax) fill_kv(buf, kt + 2);
    }

    // ---- normalize + tf32-round + write ctx (gemm2 reads raw bits) ----
    const float i0 = 1.0f / l0, i1 = 1.0f / l1;
    const size_t row0 = (size_t)b * S_LEN + qt * 128 + 16 * w + g;
    #pragma unroll
    for (int nt = 0; nt < 8; nt++) {
        const int col = h * DH + nt * 8 + 2 * tig;
        float2 o0, o1;
        o0.x = rnd_tf32(O[nt][0] * i0);  o0.y = rnd_tf32(O[nt][1] * i0);
        o1.x = rnd_tf32(O[nt][2] * i1);  o1.y = rnd_tf32(O[nt][3] * i1);
        *(float2*)(ctx + row0 * EMB + col)       = o0;
        *(float2*)(ctx + (row0 + 8) * EMB + col) = o1;
    }
}

// ===========================================================================
// Launch: pre-round -> gemm1 -> attention -> gemm2
// ===========================================================================
extern "C" void kernel_launch(void* const* d_in, const int* in_sizes, int n_in,
                              void* d_out, int out_size)
{
    const float* x     = (const float*)d_in[0];
    const float* w_in  = (const float*)d_in[1];
    const float* b_in  = (const float*)d_in[2];
    const float* w_out = (const float*)d_in[3];
    const float* b_out = (const float*)d_in[4];
    float* out = (float*)d_out;

    float *qkv = nullptr, *ctx = nullptr, *xr = nullptr, *wir = nullptr, *wor = nullptr;
    cudaGetSymbolAddress((void**)&qkv, g_qkv);
    cudaGetSymbolAddress((void**)&ctx, g_ctx);
    cudaGetSymbolAddress((void**)&xr,  g_xr);
    cudaGetSymbolAddress((void**)&wir, g_wir);
    cudaGetSymbolAddress((void**)&wor, g_wor);

    const int M = BATCH * S_LEN;   // 4096

    static bool attr_set = false;
    if (!attr_set) {
        cudaFuncSetAttribute(gemm_mma,
                             cudaFuncAttributeMaxDynamicSharedMemorySize, GM_SMEM);
        cudaFuncSetAttribute(attn_mma_kernel,
                             cudaFuncAttributeMaxDynamicSharedMemorySize, ATT_SMEM);
        attr_set = true;
    }

    // 0) pre-round GEMM operands to tf32 (RNA), once
    {
        const int nx = M * EMB / 4;            // 1048576
        const int nw = 3 * EMB * EMB / 4;      // 786432
        const int no = EMB * EMB / 4;          // 262144
        round_tf32_kernel<<<1184, 256>>>((const float4*)x,     (float4*)xr,  nx);
        round_tf32_kernel<<<1184, 256>>>((const float4*)w_in,  (float4*)wir, nw);
        round_tf32_kernel<<<1184, 256>>>((const float4*)w_out, (float4*)wor, no);
    }

    // 1) qkv = x @ in_proj_w^T + in_proj_b   [4096, 3072]
    gemm_mma<<<dim3((3 * EMB) / 128, M / 128), 256, GM_SMEM>>>(
        xr, wir, b_in, qkv, M, 3 * EMB, EMB);

    // 2) fused causal attention -> ctx [4096, 1024] (tf32-rounded)
    attn_mma_kernel<<<dim3(S_LEN / 128, BATCH * HEADS), 256, ATT_SMEM>>>(qkv, ctx);

    // 3) out = ctx @ out_proj_w^T + out_proj_b   [4096, 1024]
    gemm_mma<<<dim3(EMB / 128, M / 128), 256, GM_SMEM>>>(
        ctx, wor, b_out, out, M, EMB, EMB);
}